// round 7
// baseline (speedup 1.0000x reference)
#include <cuda_runtime.h>

#define BATCH 128
#define SEQ   512
#define DIM   768
#define MAXC  64
#define NT    256                         // 8 warps
#define NWARPS (NT / 32)
#define GROUPS 4                          // CTAs per batch
#define ROWS_PER_CTA (MAXC / GROUPS)      // 16 rows: 2 per warp

__global__ __launch_bounds__(NT, 4)
void summarizer_kernel(const float* __restrict__ enc,
                       const float* __restrict__ W,
                       const float* __restrict__ bias,
                       const int* __restrict__ cls,
                       float* __restrict__ out) {
    __shared__ float sW[DIM];
    __shared__ int   sidx[MAXC];
    __shared__ int   wtot[NWARPS];

    const int bid   = blockIdx.x;
    const int b     = bid >> 2;           // batch
    const int group = bid & 3;            // row-group (16 rows)
    const int tid   = threadIdx.x;
    const int lane  = tid & 31;
    const int warp  = tid >> 5;

    // ---- Phase 1: mask scan (2 positions/thread) + stage W to shared ----
    const int2 cv = reinterpret_cast<const int2*>(cls + (size_t)b * SEQ)[tid];
    if (tid < MAXC) sidx[tid] = -1;

    // W: 768 floats, 3 per thread, coalesced.
    sW[tid]       = W[tid];
    sW[tid + 256] = W[tid + 256];
    sW[tid + 512] = W[tid + 512];

    const int f0 = (cv.x != 0), f1 = (cv.y != 0);
    const int cnt = f0 + f1;

    int s = cnt;
    #pragma unroll
    for (int off = 1; off < 32; off <<= 1) {
        int n = __shfl_up_sync(0xffffffffu, s, off);
        if (lane >= off) s += n;
    }
    const int excl = s - cnt;
    if (lane == 31) wtot[warp] = s;
    __syncthreads();

    int base = 0;
    #pragma unroll
    for (int i = 0; i < NWARPS; i++)
        base += (i < warp) ? wtot[i] : 0;

    {
        int r = base + excl;
        const int p = tid * 2;
        if (f0) { if (r < MAXC) sidx[r] = p;     r++; }
        if (f1) { if (r < MAXC) sidx[r] = p + 1; }
    }
    __syncthreads();

    // ---- Phase 2: 2 rows per warp, 12 LDG.128 front-batched ----
    const int r0 = group * ROWS_PER_CTA + warp * 2;
    const int p0 = sidx[r0];
    const int p1 = sidx[r0 + 1];

    const float bv = bias[0];
    const float4* __restrict__ sw4 = reinterpret_cast<const float4*>(sW);

    float s0 = 0.0f, s1 = 0.0f;

    if (p1 >= 0) {
        const float4* ra = reinterpret_cast<const float4*>(enc + ((size_t)b * SEQ + p0) * DIM);
        const float4* rb = reinterpret_cast<const float4*>(enc + ((size_t)b * SEQ + p1) * DIM);
        float4 a0 = ra[lane +   0];
        float4 a1 = ra[lane +  32];
        float4 a2 = ra[lane +  64];
        float4 a3 = ra[lane +  96];
        float4 a4 = ra[lane + 128];
        float4 a5 = ra[lane + 160];
        float4 b0 = rb[lane +   0];
        float4 b1 = rb[lane +  32];
        float4 b2 = rb[lane +  64];
        float4 b3 = rb[lane +  96];
        float4 b4 = rb[lane + 128];
        float4 b5 = rb[lane + 160];
        float4 w;
        w = sw4[lane +   0]; s0 += a0.x*w.x + a0.y*w.y + a0.z*w.z + a0.w*w.w;
                             s1 += b0.x*w.x + b0.y*w.y + b0.z*w.z + b0.w*w.w;
        w = sw4[lane +  32]; s0 += a1.x*w.x + a1.y*w.y + a1.z*w.z + a1.w*w.w;
                             s1 += b1.x*w.x + b1.y*w.y + b1.z*w.z + b1.w*w.w;
        w = sw4[lane +  64]; s0 += a2.x*w.x + a2.y*w.y + a2.z*w.z + a2.w*w.w;
                             s1 += b2.x*w.x + b2.y*w.y + b2.z*w.z + b2.w*w.w;
        w = sw4[lane +  96]; s0 += a3.x*w.x + a3.y*w.y + a3.z*w.z + a3.w*w.w;
                             s1 += b3.x*w.x + b3.y*w.y + b3.z*w.z + b3.w*w.w;
        w = sw4[lane + 128]; s0 += a4.x*w.x + a4.y*w.y + a4.z*w.z + a4.w*w.w;
                             s1 += b4.x*w.x + b4.y*w.y + b4.z*w.z + b4.w*w.w;
        w = sw4[lane + 160]; s0 += a5.x*w.x + a5.y*w.y + a5.z*w.z + a5.w*w.w;
                             s1 += b5.x*w.x + b5.y*w.y + b5.z*w.z + b5.w*w.w;
    } else if (p0 >= 0) {
        const float4* ra = reinterpret_cast<const float4*>(enc + ((size_t)b * SEQ + p0) * DIM);
        float4 a0 = ra[lane +   0];
        float4 a1 = ra[lane +  32];
        float4 a2 = ra[lane +  64];
        float4 a3 = ra[lane +  96];
        float4 a4 = ra[lane + 128];
        float4 a5 = ra[lane + 160];
        float4 w;
        w = sw4[lane +   0]; s0 += a0.x*w.x + a0.y*w.y + a0.z*w.z + a0.w*w.w;
        w = sw4[lane +  32]; s0 += a1.x*w.x + a1.y*w.y + a1.z*w.z + a1.w*w.w;
        w = sw4[lane +  64]; s0 += a2.x*w.x + a2.y*w.y + a2.z*w.z + a2.w*w.w;
        w = sw4[lane +  96]; s0 += a3.x*w.x + a3.y*w.y + a3.z*w.z + a3.w*w.w;
        w = sw4[lane + 128]; s0 += a4.x*w.x + a4.y*w.y + a4.z*w.z + a4.w*w.w;
        w = sw4[lane + 160]; s0 += a5.x*w.x + a5.y*w.y + a5.z*w.z + a5.w*w.w;
    }

    #pragma unroll
    for (int off = 16; off > 0; off >>= 1) {
        s0 += __shfl_down_sync(0xffffffffu, s0, off);
        s1 += __shfl_down_sync(0xffffffffu, s1, off);
    }

    if (lane == 0) {
        out[b * MAXC + r0]     = 1.0f / (1.0f + expf(-(s0 + bv)));
        out[b * MAXC + r0 + 1] = 1.0f / (1.0f + expf(-(s1 + bv)));
    }
}

extern "C" void kernel_launch(void* const* d_in, const int* in_sizes, int n_in,
                              void* d_out, int out_size) {
    const float* enc  = (const float*)d_in[0];
    const float* W    = (const float*)d_in[1];
    const float* bias = (const float*)d_in[2];
    const int*   cls  = (const int*)d_in[3];
    float* out = (float*)d_out;

    summarizer_kernel<<<BATCH * GROUPS, NT>>>(enc, W, bias, cls, out);
}

// round 8
// speedup vs baseline: 1.0257x; 1.0257x over previous
#include <cuda_runtime.h>

#define BATCH 128
#define SEQ   512
#define DIM   768
#define MAXC  64

// Scratch: compacted indices per batch (written fully on every K1 call).
__device__ int g_sidx[BATCH * MAXC];

// ---------------- K1: per-batch compaction (128 CTAs x 128 threads) ----------------
__global__ __launch_bounds__(128)
void compact_kernel(const int* __restrict__ cls) {
    __shared__ int sidx[MAXC];
    __shared__ int wtot[4];

    const int b    = blockIdx.x;
    const int tid  = threadIdx.x;
    const int lane = tid & 31;
    const int warp = tid >> 5;

    if (tid < MAXC) sidx[tid] = -1;

    // 4 positions per thread via int4.
    const int4 cv = reinterpret_cast<const int4*>(cls + (size_t)b * SEQ)[tid];
    const int f0 = (cv.x != 0), f1 = (cv.y != 0), f2 = (cv.z != 0), f3 = (cv.w != 0);
    const int cnt = f0 + f1 + f2 + f3;

    int s = cnt;
    #pragma unroll
    for (int off = 1; off < 32; off <<= 1) {
        int n = __shfl_up_sync(0xffffffffu, s, off);
        if (lane >= off) s += n;
    }
    const int excl = s - cnt;
    if (lane == 31) wtot[warp] = s;
    __syncthreads();

    int base = 0;
    #pragma unroll
    for (int i = 0; i < 4; i++) base += (i < warp) ? wtot[i] : 0;

    {
        int r = base + excl;
        const int p = tid * 4;
        if (f0) { if (r < MAXC) sidx[r] = p;     r++; }
        if (f1) { if (r < MAXC) sidx[r] = p + 1; r++; }
        if (f2) { if (r < MAXC) sidx[r] = p + 2; r++; }
        if (f3) { if (r < MAXC) sidx[r] = p + 3; }
    }
    __syncthreads();

    if (tid < MAXC) g_sidx[b * MAXC + tid] = sidx[tid];
}

// ---------------- K2: gather + dot (1024 CTAs x 128 threads, no barriers) ----------------
__global__ __launch_bounds__(128)
void dot_kernel(const float* __restrict__ enc,
                const float* __restrict__ W,
                const float* __restrict__ bias,
                float* __restrict__ out) {
    const int lane = threadIdx.x & 31;
    const int warp = threadIdx.x >> 5;
    const int gw   = blockIdx.x * 4 + warp;   // global warp id: 4096 warps
    const int b    = gw >> 5;                 // 32 warps per batch
    const int r0   = (gw & 31) * 2;

    // Uniform 8B load of this warp's two indices (L2-hot: K1 just stored them).
    const int2 pp = *reinterpret_cast<const int2*>(g_sidx + b * MAXC + r0);
    const int p0 = pp.x, p1 = pp.y;

    const float bv = bias[0];

    if (p0 < 0) {
        if (lane == 0) {
            const float v = 1.0f / (1.0f + __expf(-bv));
            out[b * MAXC + r0]     = v;
            out[b * MAXC + r0 + 1] = v;
        }
        return;
    }

    const float4* __restrict__ w4 = reinterpret_cast<const float4*>(W);
    const float4 w0 = w4[lane +   0];
    const float4 w1 = w4[lane +  32];
    const float4 w2 = w4[lane +  64];
    const float4 w3 = w4[lane +  96];
    const float4 w4v = w4[lane + 128];
    const float4 w5 = w4[lane + 160];

    float s0 = 0.0f, s1 = 0.0f;

    if (p1 >= 0) {
        const float4* ra = reinterpret_cast<const float4*>(enc + ((size_t)b * SEQ + p0) * DIM);
        const float4* rb = reinterpret_cast<const float4*>(enc + ((size_t)b * SEQ + p1) * DIM);
        float4 a0 = ra[lane +   0];
        float4 a1 = ra[lane +  32];
        float4 a2 = ra[lane +  64];
        float4 a3 = ra[lane +  96];
        float4 a4 = ra[lane + 128];
        float4 a5 = ra[lane + 160];
        float4 b0 = rb[lane +   0];
        float4 b1 = rb[lane +  32];
        float4 b2 = rb[lane +  64];
        float4 b3 = rb[lane +  96];
        float4 b4 = rb[lane + 128];
        float4 b5 = rb[lane + 160];
        s0 += a0.x*w0.x + a0.y*w0.y + a0.z*w0.z + a0.w*w0.w;
        s0 += a1.x*w1.x + a1.y*w1.y + a1.z*w1.z + a1.w*w1.w;
        s0 += a2.x*w2.x + a2.y*w2.y + a2.z*w2.z + a2.w*w2.w;
        s0 += a3.x*w3.x + a3.y*w3.y + a3.z*w3.z + a3.w*w3.w;
        s0 += a4.x*w4v.x + a4.y*w4v.y + a4.z*w4v.z + a4.w*w4v.w;
        s0 += a5.x*w5.x + a5.y*w5.y + a5.z*w5.z + a5.w*w5.w;
        s1 += b0.x*w0.x + b0.y*w0.y + b0.z*w0.z + b0.w*w0.w;
        s1 += b1.x*w1.x + b1.y*w1.y + b1.z*w1.z + b1.w*w1.w;
        s1 += b2.x*w2.x + b2.y*w2.y + b2.z*w2.z + b2.w*w2.w;
        s1 += b3.x*w3.x + b3.y*w3.y + b3.z*w3.z + b3.w*w3.w;
        s1 += b4.x*w4v.x + b4.y*w4v.y + b4.z*w4v.z + b4.w*w4v.w;
        s1 += b5.x*w5.x + b5.y*w5.y + b5.z*w5.z + b5.w*w5.w;
    } else {
        const float4* ra = reinterpret_cast<const float4*>(enc + ((size_t)b * SEQ + p0) * DIM);
        float4 a0 = ra[lane +   0];
        float4 a1 = ra[lane +  32];
        float4 a2 = ra[lane +  64];
        float4 a3 = ra[lane +  96];
        float4 a4 = ra[lane + 128];
        float4 a5 = ra[lane + 160];
        s0 += a0.x*w0.x + a0.y*w0.y + a0.z*w0.z + a0.w*w0.w;
        s0 += a1.x*w1.x + a1.y*w1.y + a1.z*w1.z + a1.w*w1.w;
        s0 += a2.x*w2.x + a2.y*w2.y + a2.z*w2.z + a2.w*w2.w;
        s0 += a3.x*w3.x + a3.y*w3.y + a3.z*w3.z + a3.w*w3.w;
        s0 += a4.x*w4v.x + a4.y*w4v.y + a4.z*w4v.z + a4.w*w4v.w;
        s0 += a5.x*w5.x + a5.y*w5.y + a5.z*w5.z + a5.w*w5.w;
    }

    #pragma unroll
    for (int off = 16; off > 0; off >>= 1) {
        s0 += __shfl_down_sync(0xffffffffu, s0, off);
        s1 += __shfl_down_sync(0xffffffffu, s1, off);
    }

    if (lane == 0) {
        out[b * MAXC + r0] = 1.0f / (1.0f + __expf(-(s0 + bv)));
        out[b * MAXC + r0 + 1] = (p1 >= 0) ? 1.0f / (1.0f + __expf(-(s1 + bv)))
                                           : 1.0f / (1.0f + __expf(-bv));
    }
}

extern "C" void kernel_launch(void* const* d_in, const int* in_sizes, int n_in,
                              void* d_out, int out_size) {
    const float* enc  = (const float*)d_in[0];
    const float* W    = (const float*)d_in[1];
    const float* bias = (const float*)d_in[2];
    const int*   cls  = (const int*)d_in[3];
    float* out = (float*)d_out;

    compact_kernel<<<BATCH, 128>>>(cls);
    dot_kernel<<<BATCH * 32 / 4, 128>>>(enc, W, bias, out);
}